// round 14
// baseline (speedup 1.0000x reference)
#include <cuda_runtime.h>
#include <cstdint>

#define NPTS  65536
#define DIMS  512
#define KCENT 512

#define QS    20.0f                 // quantization scale
#define QSI2  (2.0f / (QS * QS))    // 2 / s^2 = 0.005

static __device__ int8_t g_ci8[KCENT * DIMS];                   // 256 KB int8 centroids
static __device__ float  g_csq[KCENT];                          // ||c||^2 (exact f32)

__device__ __forceinline__ uint32_t smem_u32(const void* p) {
    uint32_t a;
    asm("{ .reg .u64 t; cvta.to.shared.u64 t, %1; cvt.u32.u64 %0, t; }"
        : "=r"(a) : "l"(p));
    return a;
}

__device__ __forceinline__ void ldsm_x4(uint32_t addr, uint32_t* r) {
    asm volatile("ldmatrix.sync.aligned.m8n8.x4.shared.b16 {%0,%1,%2,%3}, [%4];"
                 : "=r"(r[0]), "=r"(r[1]), "=r"(r[2]), "=r"(r[3]) : "r"(addr));
}

// int8 MMA, K=32 per instruction
__device__ __forceinline__ void mma16832s8(int* d, const uint32_t* a,
                                           uint32_t b0, uint32_t b1) {
    asm volatile(
        "mma.sync.aligned.m16n8k32.row.col.s32.s8.s8.s32 "
        "{%0,%1,%2,%3}, {%4,%5,%6,%7}, {%8,%9}, {%0,%1,%2,%3};"
        : "+r"(d[0]), "+r"(d[1]), "+r"(d[2]), "+r"(d[3])
        : "r"(a[0]), "r"(a[1]), "r"(a[2]), "r"(a[3]), "r"(b0), "r"(b1));
}

__device__ __forceinline__ uint32_t pack4s8(int s0, int s1, int s2, int s3) {
    uint32_t r;
    asm("{ .reg .u32 t;\n\t"
        "cvt.pack.sat.s8.s32.b32 t, %4, %3, 0;\n\t"
        "cvt.pack.sat.s8.s32.b32 %0, %2, %1, t;\n\t"
        "}"
        : "=r"(r) : "r"(s0), "r"(s1), "r"(s2), "r"(s3));
    return r;
}

__device__ __forceinline__ float frcp(float v) {
    float r;
    asm("rcp.approx.f32 %0, %1;" : "=f"(r) : "f"(v));
    return r;
}

// ------------------------------------------------------------------
// Prepass: centroids f32 -> int8 (scale QS) + exact ||c||^2
// one warp per row
// ------------------------------------------------------------------
__global__ void __launch_bounds__(256) prep_c(const float* __restrict__ c) {
    const int wid = threadIdx.x >> 5, lane = threadIdx.x & 31;
    const int row = blockIdx.x * 8 + wid;
    const float4* src = reinterpret_cast<const float4*>(c + (size_t)row * DIMS);
    uint32_t* dst = reinterpret_cast<uint32_t*>(g_ci8 + (size_t)row * DIMS);
    float s = 0.0f;
#pragma unroll
    for (int i = 0; i < 4; i++) {
        const int j = lane + i * 32;
        float4 v = src[j];
        s = fmaf(v.x, v.x, s); s = fmaf(v.y, v.y, s);
        s = fmaf(v.z, v.z, s); s = fmaf(v.w, v.w, s);
        dst[j] = pack4s8(__float2int_rn(v.x * QS), __float2int_rn(v.y * QS),
                         __float2int_rn(v.z * QS), __float2int_rn(v.w * QS));
    }
#pragma unroll
    for (int o = 16; o > 0; o >>= 1) s += __shfl_xor_sync(0xFFFFFFFFu, s, o);
    if (lane == 0) g_csq[row] = s;
}

// ------------------------------------------------------------------
// Main fused kernel: CTA = 64 rows x 512 cols, 512 threads (16 warps),
// warp tile 32x64, int8 m16n8k32 MMA. K=64 per iteration -> 8 iters.
// Byte layout identical to the fp16 version (80B pitch, 40960B stage).
// ------------------------------------------------------------------
#define SM_CSQ   0
#define SM_XSQ   2048
#define SM_RSUM  2304
#define SM_ARING 2560             // 4 slots x (64 rows x 80B) = 20480
#define A_SLOT   5120
#define SM_BRING 23040            // 4 stages x (512 rows x 80B) = 163840
#define B_STAGE  40960
#define ROWPITCH 80
#define SMEM_TOTAL (SM_BRING + 4 * B_STAGE)   // 186880

__global__ void __launch_bounds__(512, 1)
clu_main(const float* __restrict__ x, float* __restrict__ out) {
    extern __shared__ char smem[];
    const uint32_t sb = smem_u32(smem);
    const int tid = threadIdx.x;
    const int lane = tid & 31;
    const int wid = tid >> 5;
    const int mw = wid & 1;       // 0..1  (32 rows each)
    const int nw = wid >> 1;      // 0..7  (64 cols each)
    const int m0 = blockIdx.x * 64;

    float* csq = reinterpret_cast<float*>(smem + SM_CSQ);
    float* xsq = reinterpret_cast<float*>(smem + SM_XSQ);
    float* rsum = reinterpret_cast<float*>(smem + SM_RSUM);

    csq[tid] = g_csq[tid & 511];
    if (tid < 64) {
        xsq[tid] = 1.0f;        // becomes 1 + ||x||^2 via atomicAdd
        rsum[tid] = 0.0f;
    }

    // ---- B copy: 2048 16B chunks / 512 thr = 4 each; constant strides ----
    // n = (tid>>2) + i*128 ; chunk c = tid&3 (16B of the 64B row slice)
    const int8_t* bsrc0 =
        g_ci8 + (size_t)(tid >> 2) * DIMS + (tid & 3) * 16;            // + i*65536 B
    const uint32_t bdst0 = sb + SM_BRING + (tid >> 2) * ROWPITCH + (tid & 3) * 16; // + i*10240

#define ISSUE_B(stage, k0) do {                                               \
        const uint32_t _soff = (stage) * B_STAGE;                             \
        const int _koff = (k0) * 64;                                          \
        asm volatile("cp.async.cg.shared.global [%0], [%1], 16;"              \
            :: "r"(bdst0 + _soff), "l"(bsrc0 + _koff) : "memory");            \
        asm volatile("cp.async.cg.shared.global [%0], [%1], 16;"              \
            :: "r"(bdst0 + _soff + 10240), "l"(bsrc0 + _koff + 65536) : "memory"); \
        asm volatile("cp.async.cg.shared.global [%0], [%1], 16;"              \
            :: "r"(bdst0 + _soff + 20480), "l"(bsrc0 + _koff + 131072) : "memory"); \
        asm volatile("cp.async.cg.shared.global [%0], [%1], 16;"              \
            :: "r"(bdst0 + _soff + 30720), "l"(bsrc0 + _koff + 196608) : "memory"); \
        asm volatile("cp.async.commit_group;" ::: "memory");                  \
    } while (0)

    // ---- A copy: 512 threads, 8 floats -> 8 int8 (8B) each per iter ----
    // row = tid>>3 (0..63), chunk = tid&7 (8 floats each); K=64 per iter
    const float* arow = x + (size_t)(m0 + (tid >> 3)) * DIMS + (tid & 7) * 8;
    const uint32_t adst = sb + SM_ARING + (tid >> 3) * ROWPITCH + (tid & 7) * 8;
    float pxsq = 0.0f;
    float4 ha0, ha1;   // held A prefetch for iter "it+2"

#define CVT_STS_A(slot, v0, v1) do {                                          \
        pxsq = fmaf((v0).x, (v0).x, pxsq); pxsq = fmaf((v0).y, (v0).y, pxsq); \
        pxsq = fmaf((v0).z, (v0).z, pxsq); pxsq = fmaf((v0).w, (v0).w, pxsq); \
        pxsq = fmaf((v1).x, (v1).x, pxsq); pxsq = fmaf((v1).y, (v1).y, pxsq); \
        pxsq = fmaf((v1).z, (v1).z, pxsq); pxsq = fmaf((v1).w, (v1).w, pxsq); \
        uint32_t p0 = pack4s8(__float2int_rn((v0).x * QS), __float2int_rn((v0).y * QS), \
                              __float2int_rn((v0).z * QS), __float2int_rn((v0).w * QS)); \
        uint32_t p1 = pack4s8(__float2int_rn((v1).x * QS), __float2int_rn((v1).y * QS), \
                              __float2int_rn((v1).z * QS), __float2int_rn((v1).w * QS)); \
        asm volatile("st.shared.v2.b32 [%0], {%1,%2};"                        \
                     :: "r"(adst + (slot) * A_SLOT), "r"(p0), "r"(p1) : "memory"); \
    } while (0)

    // ---- prologue: A slots 0,1 stored + iter-2 data held; B stages 0,1 ----
    {
        const float4* s0 = reinterpret_cast<const float4*>(arow);
        const float4* s1 = reinterpret_cast<const float4*>(arow + 64);
        const float4* s2 = reinterpret_cast<const float4*>(arow + 128);
        float4 a00 = s0[0], a01 = s0[1];
        float4 a10 = s1[0], a11 = s1[1];
        ha0 = s2[0]; ha1 = s2[1];
        CVT_STS_A(0, a00, a01);
        CVT_STS_A(1, a10, a11);
    }
    ISSUE_B(0, 0);
    ISSUE_B(1, 1);

    // s32 accumulators: 2 mt x 8 nt x 4 = 64 regs
    int acc[2][8][4];
#pragma unroll
    for (int mt = 0; mt < 2; mt++)
#pragma unroll
        for (int nt = 0; nt < 8; nt++)
#pragma unroll
            for (int c = 0; c < 4; c++) acc[mt][nt][c] = 0;

    // ldmatrix lane address components (byte-identical to fp16 layout)
    const int g = lane >> 3;
    const int row_off = (lane & 7) + (g & 1) * 8;
    const int kb = (g >> 1) * 16;
    const uint32_t a_base = sb + SM_ARING + (mw * 32 + row_off) * ROWPITCH + kb;
    const uint32_t b_base = sb + SM_BRING + (nw * 64 + row_off) * ROWPITCH + kb;

#define MMA_HALF(abuf, bA, bB, p0i) do {                                      \
        mma16832s8(acc[0][2*(p0i)],     (abuf)[0], (bA)[0], (bA)[2]);         \
        mma16832s8(acc[0][2*(p0i)+1],   (abuf)[0], (bA)[1], (bA)[3]);         \
        mma16832s8(acc[1][2*(p0i)],     (abuf)[1], (bA)[0], (bA)[2]);         \
        mma16832s8(acc[1][2*(p0i)+1],   (abuf)[1], (bA)[1], (bA)[3]);         \
        mma16832s8(acc[0][2*(p0i)+2],   (abuf)[0], (bB)[0], (bB)[2]);         \
        mma16832s8(acc[0][2*(p0i)+3],   (abuf)[0], (bB)[1], (bB)[3]);         \
        mma16832s8(acc[1][2*(p0i)+2],   (abuf)[1], (bB)[0], (bB)[2]);         \
        mma16832s8(acc[1][2*(p0i)+3],   (abuf)[1], (bB)[1], (bB)[3]);         \
    } while (0)

#pragma unroll 1
    for (int it = 0; it < 8; ++it) {
        if (it < 6) asm volatile("cp.async.wait_group 1;" ::: "memory");
        else        asm volatile("cp.async.wait_group 0;" ::: "memory");
        __syncthreads();   // the ONLY barrier this iteration

        if (it + 2 < 8) {
            ISSUE_B((it + 2) & 3, it + 2);
            CVT_STS_A((it + 2) & 3, ha0, ha1);
            if (it + 3 < 8) {
                const float4* src =
                    reinterpret_cast<const float4*>(arow + (it + 3) * 64);
                ha0 = src[0]; ha1 = src[1];
            }
        }

        const uint32_t a_row = a_base + (it & 3) * A_SLOT;
        const uint32_t b_row = b_base + (it & 3) * B_STAGE;

        // ---- software-pipelined fragment schedule (4 half-steps) ----
        // k-step = 32 int8 = 32 bytes; two k-steps per iteration
        uint32_t aA[2][4], aB[2][4];
        uint32_t b0[4], b1[4], b2[4], b3[4], b4[4], b5[4], b6[4], b7[4];
        ldsm_x4(a_row, aA[0]);
        ldsm_x4(a_row + 16 * ROWPITCH, aA[1]);
        ldsm_x4(b_row, b0);
        ldsm_x4(b_row + 16 * ROWPITCH, b1);
        ldsm_x4(b_row + 32 * ROWPITCH, b2);
        ldsm_x4(b_row + 48 * ROWPITCH, b3);
        MMA_HALF(aA, b0, b1, 0);
        ldsm_x4(a_row + 32, aB[0]);
        ldsm_x4(a_row + 16 * ROWPITCH + 32, aB[1]);
        ldsm_x4(b_row + 32, b4);
        ldsm_x4(b_row + 16 * ROWPITCH + 32, b5);
        MMA_HALF(aA, b2, b3, 2);
        ldsm_x4(b_row + 32 * ROWPITCH + 32, b6);
        ldsm_x4(b_row + 48 * ROWPITCH + 32, b7);
        MMA_HALF(aB, b4, b5, 0);
        MMA_HALF(aB, b6, b7, 2);
    }

    // finish ||x||^2: 8 partial sums per row (exact f32)
    atomicAdd(&xsq[tid >> 3], pxsq);
    __syncthreads();

    // ---- Epilogue: q = rcp(1+||x||^2+||c||^2 - 2*dot/s^2); rowsum; norm ----
    const int rquad = lane >> 2;
    const int cpair = (lane & 3) * 2;

#pragma unroll
    for (int mt = 0; mt < 2; mt++) {
        const float xlo = xsq[mw * 32 + mt * 16 + rquad];
        const float xhi = xsq[mw * 32 + mt * 16 + rquad + 8];
        float slo = 0.0f, shi = 0.0f;
#pragma unroll
        for (int nt = 0; nt < 8; nt++) {
            const int col = nw * 64 + nt * 8 + cpair;
            const float c0 = csq[col], c1 = csq[col + 1];
            float q0 = frcp(fmaf(-QSI2, (float)acc[mt][nt][0], xlo + c0));
            float q1 = frcp(fmaf(-QSI2, (float)acc[mt][nt][1], xlo + c1));
            float q2 = frcp(fmaf(-QSI2, (float)acc[mt][nt][2], xhi + c0));
            float q3 = frcp(fmaf(-QSI2, (float)acc[mt][nt][3], xhi + c1));
            slo += q0 + q1; shi += q2 + q3;
        }
        slo += __shfl_xor_sync(0xFFFFFFFFu, slo, 1);
        slo += __shfl_xor_sync(0xFFFFFFFFu, slo, 2);
        shi += __shfl_xor_sync(0xFFFFFFFFu, shi, 1);
        shi += __shfl_xor_sync(0xFFFFFFFFu, shi, 2);
        if ((lane & 3) == 0) {
            atomicAdd(&rsum[mw * 32 + mt * 16 + rquad], slo);
            atomicAdd(&rsum[mw * 32 + mt * 16 + rquad + 8], shi);
        }
    }
    __syncthreads();

#pragma unroll
    for (int mt = 0; mt < 2; mt++) {
        const int rlo = mw * 32 + mt * 16 + rquad;
        const float xl = xsq[rlo];
        const float xh = xsq[rlo + 8];
        const float ilo = frcp(rsum[rlo]);
        const float ihi = frcp(rsum[rlo + 8]);
        float* olo = out + (size_t)(m0 + rlo) * KCENT;
        float* ohi = out + (size_t)(m0 + rlo + 8) * KCENT;
#pragma unroll
        for (int nt = 0; nt < 8; nt++) {
            const int col = nw * 64 + nt * 8 + cpair;
            const float c0 = csq[col], c1 = csq[col + 1];
            float q0 = frcp(fmaf(-QSI2, (float)acc[mt][nt][0], xl + c0)) * ilo;
            float q1 = frcp(fmaf(-QSI2, (float)acc[mt][nt][1], xl + c1)) * ilo;
            float q2 = frcp(fmaf(-QSI2, (float)acc[mt][nt][2], xh + c0)) * ihi;
            float q3 = frcp(fmaf(-QSI2, (float)acc[mt][nt][3], xh + c1)) * ihi;
            *reinterpret_cast<float2*>(olo + col) = make_float2(q0, q1);
            *reinterpret_cast<float2*>(ohi + col) = make_float2(q2, q3);
        }
    }
}

// ------------------------------------------------------------------
extern "C" void kernel_launch(void* const* d_in, const int* in_sizes, int n_in,
                              void* d_out, int out_size) {
    (void)in_sizes; (void)n_in; (void)out_size;
    const float* x = (const float*)d_in[0];   // [65536, 512] f32
    const float* c = (const float*)d_in[1];   // [512, 512] f32
    float* out = (float*)d_out;               // [65536, 512] f32

    prep_c<<<KCENT / 8, 256>>>(c);

    static bool attr_set = false;
    if (!attr_set) {
        cudaFuncSetAttribute(clu_main, cudaFuncAttributeMaxDynamicSharedMemorySize,
                             SMEM_TOTAL);
        attr_set = true;
    }
    clu_main<<<NPTS / 64, 512, SMEM_TOTAL>>>(x, out);
}

// round 15
// speedup vs baseline: 1.6886x; 1.6886x over previous
#include <cuda_runtime.h>
#include <cuda_bf16.h>
#include <cstdint>

#define NPTS  65536
#define DIMS  512
#define KCENT 512

static __device__ __nv_bfloat16 g_cbf16[KCENT * DIMS];          // 512 KB
static __device__ float        g_csq[KCENT];                    // ||c||^2

__device__ __forceinline__ uint32_t smem_u32(const void* p) {
    uint32_t a;
    asm("{ .reg .u64 t; cvta.to.shared.u64 t, %1; cvt.u32.u64 %0, t; }"
        : "=r"(a) : "l"(p));
    return a;
}

__device__ __forceinline__ void ldsm_x4(uint32_t addr, uint32_t* r) {
    asm volatile("ldmatrix.sync.aligned.m8n8.x4.shared.b16 {%0,%1,%2,%3}, [%4];"
                 : "=r"(r[0]), "=r"(r[1]), "=r"(r[2]), "=r"(r[3]) : "r"(addr));
}

__device__ __forceinline__ void mma16816(float* d, const uint32_t* a,
                                         uint32_t b0, uint32_t b1) {
    asm volatile(
        "mma.sync.aligned.m16n8k16.row.col.f32.bf16.bf16.f32 "
        "{%0,%1,%2,%3}, {%4,%5,%6,%7}, {%8,%9}, {%0,%1,%2,%3};"
        : "+f"(d[0]), "+f"(d[1]), "+f"(d[2]), "+f"(d[3])
        : "r"(a[0]), "r"(a[1]), "r"(a[2]), "r"(a[3]), "r"(b0), "r"(b1));
}

__device__ __forceinline__ float frcp(float v) {
    float r;
    asm("rcp.approx.f32 %0, %1;" : "=f"(r) : "f"(v));
    return r;
}

// ------------------------------------------------------------------
// Prepass: centroids f32 -> bf16 + ||c||^2 (one warp per row)
// ------------------------------------------------------------------
__global__ void __launch_bounds__(256) prep_c(const float* __restrict__ c) {
    const int wid = threadIdx.x >> 5, lane = threadIdx.x & 31;
    const int row = blockIdx.x * 8 + wid;
    const float4* src = reinterpret_cast<const float4*>(c + (size_t)row * DIMS);
    uint2* dst = reinterpret_cast<uint2*>(g_cbf16 + (size_t)row * DIMS);
    float s = 0.0f;
#pragma unroll
    for (int i = 0; i < 4; i++) {
        float4 v = src[lane + i * 32];
        s = fmaf(v.x, v.x, s); s = fmaf(v.y, v.y, s);
        s = fmaf(v.z, v.z, s); s = fmaf(v.w, v.w, s);
        __nv_bfloat162 p0 = __floats2bfloat162_rn(v.x, v.y);
        __nv_bfloat162 p1 = __floats2bfloat162_rn(v.z, v.w);
        uint2 u;
        u.x = *reinterpret_cast<uint32_t*>(&p0);
        u.y = *reinterpret_cast<uint32_t*>(&p1);
        dst[lane + i * 32] = u;
    }
#pragma unroll
    for (int o = 16; o > 0; o >>= 1) s += __shfl_xor_sync(0xFFFFFFFFu, s, o);
    if (lane == 0) g_csq[row] = s;
}

// ------------------------------------------------------------------
// Main fused kernel: CTA = 64 rows x 512 cols, 512 threads (16 warps),
// warp tile 32x64. CUTLASS-multistage style: fragment register double
// buffering — LDSM of k-step s+1 (incl. next tile's ks0) overlaps the
// MMAs of k-step s. wait_group+__syncthreads sits MID-iteration.
// ------------------------------------------------------------------
#define SM_CSQ   0
#define SM_XSQ   2048
#define SM_RSUM  2304
#define SM_ARING 2560             // 4 slots x (64 rows x 80B) = 20480
#define A_SLOT   5120
#define SM_BRING 23040            // 4 stages x (512 rows x 80B) = 163840
#define B_STAGE  40960
#define ROWPITCH 80
#define SMEM_TOTAL (SM_BRING + 4 * B_STAGE)   // 186880

__global__ void __launch_bounds__(512, 1)
clu_main(const float* __restrict__ x, float* __restrict__ out) {
    extern __shared__ char smem[];
    const uint32_t sb = smem_u32(smem);
    const int tid = threadIdx.x;
    const int lane = tid & 31;
    const int wid = tid >> 5;
    const int mw = wid & 1;       // 0..1  (32 rows each)
    const int nw = wid >> 1;      // 0..7  (64 cols each)
    const int m0 = blockIdx.x * 64;

    float* csq = reinterpret_cast<float*>(smem + SM_CSQ);
    float* xsq = reinterpret_cast<float*>(smem + SM_XSQ);
    float* rsum = reinterpret_cast<float*>(smem + SM_RSUM);

    csq[tid] = g_csq[tid & 511];
    if (tid < 64) {
        xsq[tid] = 1.0f;        // becomes 1 + ||x||^2 via atomicAdd
        rsum[tid] = 0.0f;
    }

    // ---- B copy bases: 4 16B chunks per thread; constant strides ----
    const __nv_bfloat16* bsrc0 =
        g_cbf16 + (size_t)(tid >> 2) * DIMS + (tid & 3) * 8;           // + i*65536 elems
    const uint32_t bdst0 = sb + SM_BRING + (tid >> 2) * ROWPITCH + (tid & 3) * 16; // + i*10240

#define ISSUE_B(stage, k0) do {                                               \
        const uint32_t _soff = (stage) * B_STAGE;                             \
        const int _koff = (k0) * 32;                                          \
        asm volatile("cp.async.cg.shared.global [%0], [%1], 16;"              \
            :: "r"(bdst0 + _soff), "l"(bsrc0 + _koff) : "memory");            \
        asm volatile("cp.async.cg.shared.global [%0], [%1], 16;"              \
            :: "r"(bdst0 + _soff + 10240), "l"(bsrc0 + _koff + 65536) : "memory"); \
        asm volatile("cp.async.cg.shared.global [%0], [%1], 16;"              \
            :: "r"(bdst0 + _soff + 20480), "l"(bsrc0 + _koff + 131072) : "memory"); \
        asm volatile("cp.async.cg.shared.global [%0], [%1], 16;"              \
            :: "r"(bdst0 + _soff + 30720), "l"(bsrc0 + _koff + 196608) : "memory"); \
        asm volatile("cp.async.commit_group;" ::: "memory");                  \
    } while (0)

    // ---- A copy: ALL 512 threads, one float4 (4 f32 -> 8B bf16) each ----
    const float* arow = x + (size_t)(m0 + (tid >> 3)) * DIMS + (tid & 7) * 4;
    const uint32_t adst = sb + SM_ARING + (tid >> 3) * ROWPITCH + (tid & 7) * 8;
    float pxsq = 0.0f;
    float4 ha;   // held A prefetch for tile "it+2"

#define CVT_STS_A(slot, v) do {                                               \
        pxsq = fmaf((v).x, (v).x, pxsq); pxsq = fmaf((v).y, (v).y, pxsq);     \
        pxsq = fmaf((v).z, (v).z, pxsq); pxsq = fmaf((v).w, (v).w, pxsq);     \
        __nv_bfloat162 p0 = __floats2bfloat162_rn((v).x, (v).y);              \
        __nv_bfloat162 p1 = __floats2bfloat162_rn((v).z, (v).w);              \
        asm volatile("st.shared.v2.b32 [%0], {%1,%2};"                        \
                     :: "r"(adst + (slot) * A_SLOT),                          \
                        "r"(*reinterpret_cast<uint32_t*>(&p0)),               \
                        "r"(*reinterpret_cast<uint32_t*>(&p1)) : "memory");   \
    } while (0)

    // ---- prologue: A slots 0,1 stored + tile 2 held; B stages 0,1,2 ----
    {
        const float4 v0 = *reinterpret_cast<const float4*>(arow);
        const float4 v1 = *reinterpret_cast<const float4*>(arow + 32);
        ha = *reinterpret_cast<const float4*>(arow + 64);
        CVT_STS_A(0, v0);
        CVT_STS_A(1, v1);
    }
    ISSUE_B(0, 0);
    ISSUE_B(1, 1);
    ISSUE_B(2, 2);

    float acc[2][8][4];
#pragma unroll
    for (int mt = 0; mt < 2; mt++)
#pragma unroll
        for (int nt = 0; nt < 8; nt++)
#pragma unroll
            for (int c = 0; c < 4; c++) acc[mt][nt][c] = 0.0f;

    // ldmatrix lane address components
    const int g = lane >> 3;
    const int row_off = (lane & 7) + (g & 1) * 8;
    const int kb = (g >> 1) * 16;
    const uint32_t a_base = sb + SM_ARING + (mw * 32 + row_off) * ROWPITCH + kb;
    const uint32_t b_base = sb + SM_BRING + (nw * 64 + row_off) * ROWPITCH + kb;

    // fragment double buffers: buf0 = current k-step, buf1 = in-flight
    uint32_t fa0[2][4], fb0[4][4];   // ks frags (A: 2 m-tiles, B: 4 ldsm = 8 n-tiles)
    uint32_t fa1[2][4], fb1[4][4];

#define LDSM_STEP(fa, fb, a_addr, b_addr) do {                                \
        ldsm_x4((a_addr), (fa)[0]);                                           \
        ldsm_x4((a_addr) + 16 * ROWPITCH, (fa)[1]);                           \
        ldsm_x4((b_addr), (fb)[0]);                                           \
        ldsm_x4((b_addr) + 16 * ROWPITCH, (fb)[1]);                           \
        ldsm_x4((b_addr) + 32 * ROWPITCH, (fb)[2]);                           \
        ldsm_x4((b_addr) + 48 * ROWPITCH, (fb)[3]);                           \
    } while (0)

    // 16 MMAs consuming one k-step's fragments
#define MMA_STEP(fa, fb) do {                                                 \
        mma16816(acc[0][0], (fa)[0], (fb)[0][0], (fb)[0][2]);                 \
        mma16816(acc[0][1], (fa)[0], (fb)[0][1], (fb)[0][3]);                 \
        mma16816(acc[1][0], (fa)[1], (fb)[0][0], (fb)[0][2]);                 \
        mma16816(acc[1][1], (fa)[1], (fb)[0][1], (fb)[0][3]);                 \
        mma16816(acc[0][2], (fa)[0], (fb)[1][0], (fb)[1][2]);                 \
        mma16816(acc[0][3], (fa)[0], (fb)[1][1], (fb)[1][3]);                 \
        mma16816(acc[1][2], (fa)[1], (fb)[1][0], (fb)[1][2]);                 \
        mma16816(acc[1][3], (fa)[1], (fb)[1][1], (fb)[1][3]);                 \
        mma16816(acc[0][4], (fa)[0], (fb)[2][0], (fb)[2][2]);                 \
        mma16816(acc[0][5], (fa)[0], (fb)[2][1], (fb)[2][3]);                 \
        mma16816(acc[1][4], (fa)[1], (fb)[2][0], (fb)[2][2]);                 \
        mma16816(acc[1][5], (fa)[1], (fb)[2][1], (fb)[2][3]);                 \
        mma16816(acc[0][6], (fa)[0], (fb)[3][0], (fb)[3][2]);                 \
        mma16816(acc[0][7], (fa)[0], (fb)[3][1], (fb)[3][3]);                 \
        mma16816(acc[1][6], (fa)[1], (fb)[3][0], (fb)[3][2]);                 \
        mma16816(acc[1][7], (fa)[1], (fb)[3][1], (fb)[3][3]);                 \
    } while (0)

    // prologue frag load: tile 0 ks0 (stage 0 certified resident + visible)
    asm volatile("cp.async.wait_group 2;" ::: "memory");
    __syncthreads();
    LDSM_STEP(fa0, fb0, a_base, b_base);

#pragma unroll 1
    for (int it = 0; it < 16; ++it) {
        // ring slot (it+3)&3 freed by iter (it-1)'s mid-barrier
        if (it + 3 < 16) ISSUE_B((it + 3) & 3, it + 3);
        if (it + 2 < 16) {
            CVT_STS_A((it + 2) & 3, ha);
            if (it + 3 < 16)
                ha = *reinterpret_cast<const float4*>(arow + (it + 3) * 32);
        }

        const uint32_t a_row = a_base + (it & 3) * A_SLOT;
        const uint32_t b_row = b_base + (it & 3) * B_STAGE;

        // LDSM ks1(tile it) overlaps MMA ks0
        LDSM_STEP(fa1, fb1, a_row + 32, b_row + 32);
        MMA_STEP(fa0, fb0);

        // mid-iteration stage handoff: certify stage it+1 resident+visible,
        // and free slot (it)&3 / A slot for next iteration's issues
        if (it <= 12)      asm volatile("cp.async.wait_group 2;" ::: "memory");
        else if (it == 13) asm volatile("cp.async.wait_group 1;" ::: "memory");
        else               asm volatile("cp.async.wait_group 0;" ::: "memory");
        __syncthreads();

        // LDSM ks0(tile it+1) overlaps MMA ks1
        if (it + 1 < 16) {
            const uint32_t a_next = a_base + ((it + 1) & 3) * A_SLOT;
            const uint32_t b_next = b_base + ((it + 1) & 3) * B_STAGE;
            LDSM_STEP(fa0, fb0, a_next, b_next);
        }
        MMA_STEP(fa1, fb1);
    }

    // finish ||x||^2: 8 partial sums per row (all 512 threads)
    atomicAdd(&xsq[tid >> 3], pxsq);
    __syncthreads();

    // ---- Epilogue: q = rcp(1 + ||x||^2 + ||c||^2 - 2 acc); rowsum; norm ----
    const int rquad = lane >> 2;
    const int cpair = (lane & 3) * 2;

#pragma unroll
    for (int mt = 0; mt < 2; mt++) {
        const float xlo = xsq[mw * 32 + mt * 16 + rquad];
        const float xhi = xsq[mw * 32 + mt * 16 + rquad + 8];
        float slo = 0.0f, shi = 0.0f;
#pragma unroll
        for (int nt = 0; nt < 8; nt++) {
            const int col = nw * 64 + nt * 8 + cpair;
            const float c0 = csq[col], c1 = csq[col + 1];
            float q0 = frcp(fmaf(-2.0f, acc[mt][nt][0], xlo + c0));
            float q1 = frcp(fmaf(-2.0f, acc[mt][nt][1], xlo + c1));
            float q2 = frcp(fmaf(-2.0f, acc[mt][nt][2], xhi + c0));
            float q3 = frcp(fmaf(-2.0f, acc[mt][nt][3], xhi + c1));
            acc[mt][nt][0] = q0; acc[mt][nt][1] = q1;
            acc[mt][nt][2] = q2; acc[mt][nt][3] = q3;
            slo += q0 + q1; shi += q2 + q3;
        }
        slo += __shfl_xor_sync(0xFFFFFFFFu, slo, 1);
        slo += __shfl_xor_sync(0xFFFFFFFFu, slo, 2);
        shi += __shfl_xor_sync(0xFFFFFFFFu, shi, 1);
        shi += __shfl_xor_sync(0xFFFFFFFFu, shi, 2);
        if ((lane & 3) == 0) {
            atomicAdd(&rsum[mw * 32 + mt * 16 + rquad], slo);
            atomicAdd(&rsum[mw * 32 + mt * 16 + rquad + 8], shi);
        }
    }
    __syncthreads();

#pragma unroll
    for (int mt = 0; mt < 2; mt++) {
        const int rlo = mw * 32 + mt * 16 + rquad;
        const float ilo = frcp(rsum[rlo]);
        const float ihi = frcp(rsum[rlo + 8]);
        float* olo = out + (size_t)(m0 + rlo) * KCENT;
        float* ohi = out + (size_t)(m0 + rlo + 8) * KCENT;
#pragma unroll
        for (int nt = 0; nt < 8; nt++) {
            const int col = nw * 64 + nt * 8 + cpair;
            float2 vlo = make_float2(acc[mt][nt][0] * ilo, acc[mt][nt][1] * ilo);
            float2 vhi = make_float2(acc[mt][nt][2] * ihi, acc[mt][nt][3] * ihi);
            *reinterpret_cast<float2*>(olo + col) = vlo;
            *reinterpret_cast<float2*>(ohi + col) = vhi;
        }
    }
}

// ------------------------------------------------------------------
extern "C" void kernel_launch(void* const* d_in, const int* in_sizes, int n_in,
                              void* d_out, int out_size) {
    (void)in_sizes; (void)n_in; (void)out_size;
    const float* x = (const float*)d_in[0];   // [65536, 512] f32
    const float* c = (const float*)d_in[1];   // [512, 512] f32
    float* out = (float*)d_out;               // [65536, 512] f32

    prep_c<<<KCENT / 8, 256>>>(c);

    static bool attr_set = false;
    if (!attr_set) {
        cudaFuncSetAttribute(clu_main, cudaFuncAttributeMaxDynamicSharedMemorySize,
                             SMEM_TOTAL);
        attr_set = true;
    }
    clu_main<<<NPTS / 64, 512, SMEM_TOTAL>>>(x, out);
}